// round 12
// baseline (speedup 1.0000x reference)
#include <cuda_runtime.h>
#include <cuda_fp16.h>
#include <stdint.h>

// Problem constants
#define NN   20000
#define EE   640000
#define FIN  128
#define FOUT 128
#define RR   65
#define BB   65
#define TILE_M 256
#define NBN  200

#define ROWB 272                   // bytes per smem tile row (136 halves, padded)
#define ATILE (TILE_M * ROWB)      // 69632 B
#define BTILE (128 * ROWB)         // 34816 B
#define GEMM_GRID 148              // 1 CTA per SM, 16 warps

// ---------------- scratch (__device__ globals) ------------------------------
__device__ __align__(16) __half g_WT[(size_t)RR * FOUT * FIN];   // [r][o][k] fp16
__device__ __align__(16) __half g_xh[(size_t)NN * FIN];
__device__ int   g_cnt[RR];
__device__ int   g_rcur[RR];
__device__ int   g_estart[RR + 1];
__device__ int   g_tstart[RR + 1];
__device__ int   g_perm[EE];
__device__ int   g_dcnt[NN];
__device__ int   g_dcur[NN];
__device__ int   g_dstart[NN + 1];
__device__ int   g_bsum[20];
__device__ int   g_boff[20];
__device__ int   g_dinv[EE];                     // edge -> dst-sorted rank
__device__ __align__(16) __half g_edge_out[(size_t)EE * FOUT]; // dst-rank order
__device__ float g_res[(size_t)NN * FOUT];
__device__ float g_h[(size_t)NN * FOUT];
__device__ float g_psum[NBN * FOUT];
__device__ float g_psq[NBN * FOUT];
__device__ float g_scale[FOUT];
__device__ float g_shift[FOUT];

// ---------------- helpers ----------------------------------------------------
__device__ __forceinline__ uint32_t smem_u32(const void* p) {
    uint32_t a;
    asm("{ .reg .u64 t; cvta.to.shared.u64 t, %1; cvt.u32.u64 %0, t; }"
        : "=r"(a) : "l"(p));
    return a;
}

__device__ __forceinline__ void ldsm_x4(uint32_t addr, uint32_t& r0, uint32_t& r1,
                                        uint32_t& r2, uint32_t& r3) {
    asm volatile("ldmatrix.sync.aligned.m8n8.x4.shared.b16 {%0,%1,%2,%3}, [%4];"
                 : "=r"(r0), "=r"(r1), "=r"(r2), "=r"(r3) : "r"(addr));
}

// fp16-accumulator HMMA
__device__ __forceinline__ void mma16816h(uint32_t* c, const uint32_t* a,
                                          uint32_t b0, uint32_t b1) {
    asm volatile(
        "mma.sync.aligned.m16n8k16.row.col.f16.f16.f16.f16 "
        "{%0,%1}, {%2,%3,%4,%5}, {%6,%7}, {%0,%1};"
        : "+r"(c[0]), "+r"(c[1])
        : "r"(a[0]), "r"(a[1]), "r"(a[2]), "r"(a[3]), "r"(b0), "r"(b1));
}

__device__ __forceinline__ void cp16(uint32_t dst, const void* src) {
    asm volatile("cp.async.cg.shared.global [%0], [%1], 16;"
                 :: "r"(dst), "l"(src) : "memory");
}
#define CP_COMMIT() asm volatile("cp.async.commit_group;" ::: "memory")
#define CP_WAIT0()  asm volatile("cp.async.wait_group 0;" ::: "memory")

// ---------------- K1: WT fp16 = (comp x basis) transposed, basis read once -----
__global__ __launch_bounds__(128) void k_w(const float* __restrict__ basis,
                                           const float* __restrict__ comp) {
    extern __shared__ float swm[];
    float* sb = swm;              // [BB][FIN] = basis[b][i][o] for fixed i
    float* sc = swm + BB * FIN;   // [RR*BB]

    int i = blockIdx.x, o = threadIdx.x;

    for (int b = 0; b < BB; b++)
        sb[b * FIN + o] = basis[(size_t)b * FIN * FOUT + (size_t)i * FOUT + o];
    for (int idx = o; idx < RR * BB; idx += 128)
        sc[idx] = comp[idx];
    __syncthreads();

    float acc[RR];
    #pragma unroll
    for (int r = 0; r < RR; r++) acc[r] = 0.f;

    for (int b = 0; b < BB; b++) {
        float sv = sb[b * FIN + o];
        #pragma unroll
        for (int r = 0; r < RR; r++)
            acc[r] += sc[r * BB + b] * sv;
    }

    #pragma unroll 1
    for (int r = 0; r < RR; r++)
        g_WT[((size_t)r * FOUT + o) * FIN + i] = __float2half(acc[r]);
}

// ---------------- K1b: x -> fp16; also zero counters ---------------------------
__global__ void k_xcvt(const float* __restrict__ x) {
    int i = blockIdx.x * 256 + threadIdx.x;          // half2 index
    if (i < NN * FIN / 2) {
        float2 v = ((const float2*)x)[i];
        ((__half2*)g_xh)[i] = __floats2half2_rn(v.x, v.y);
    }
    if (i < NN) { g_dcnt[i] = 0; g_dcur[i] = 0; }
    if (i < RR) { g_cnt[i] = 0; g_rcur[i] = 0; }
}

// ---------------- K2: histograms ------------------------------------------------
__global__ void k_hist(const int* __restrict__ etype, const int* __restrict__ dst) {
    __shared__ int sh[RR];
    int tid = threadIdx.x;
    if (tid < RR) sh[tid] = 0;
    __syncthreads();
    int e = blockIdx.x * 256 + tid;
    if (e < EE) {
        atomicAdd(&sh[etype[e]], 1);
        atomicAdd(&g_dcnt[dst[e]], 1);
    }
    __syncthreads();
    if (tid < RR && sh[tid]) atomicAdd(&g_cnt[tid], sh[tid]);
}

// ---------------- K3a: local scans (20 blocks x 1000 counts) --------------------
__global__ __launch_bounds__(1024) void k_scan1() {
    __shared__ int sa[1024], sb2[1024];
    int t = threadIdx.x;
    int g = blockIdx.x * 1000;
    int v = (t < 1000) ? g_dcnt[g + t] : 0;
    sa[t] = v;
    __syncthreads();
    int* in = sa; int* out = sb2;
    #pragma unroll
    for (int off = 1; off < 1024; off <<= 1) {
        out[t] = in[t] + ((t >= off) ? in[t - off] : 0);
        __syncthreads();
        int* tmp = in; in = out; out = tmp;
    }
    if (t < 1000) g_dstart[g + t] = in[t] - v;      // local exclusive
    if (t == 999) g_bsum[blockIdx.x] = in[t];       // block total
}

// ---------------- K3b: block offsets + relation scan ------------------------------
__global__ void k_scan2() {
    if (threadIdx.x == 0) {
        int run = 0;
        for (int k = 0; k < 20; k++) { g_boff[k] = run; run += g_bsum[k]; }
        g_dstart[NN] = run;
        int es = 0, ts = 0;
        for (int r = 0; r < RR; r++) {
            g_estart[r] = es; g_tstart[r] = ts;
            es += g_cnt[r];
            ts += (g_cnt[r] + TILE_M - 1) / TILE_M;
        }
        g_estart[RR] = es; g_tstart[RR] = ts;
    }
}

// ---------------- K3c: add block offsets -------------------------------------------
__global__ __launch_bounds__(1024) void k_scan3() {
    int t = threadIdx.x;
    if (t < 1000) g_dstart[blockIdx.x * 1000 + t] += g_boff[blockIdx.x];
}

// ---------------- K4: scatter ------------------------------------------------------
__global__ void k_scatter(const int* __restrict__ etype, const int* __restrict__ dst) {
    __shared__ int s_cnt[RR], s_base[RR];
    int tid = threadIdx.x;
    if (tid < RR) s_cnt[tid] = 0;
    __syncthreads();
    int e = blockIdx.x * 256 + tid;
    bool valid = (e < EE);
    int r = 0, lrank = 0;
    if (valid) { r = etype[e]; lrank = atomicAdd(&s_cnt[r], 1); }
    __syncthreads();
    if (tid < RR && s_cnt[tid] > 0) s_base[tid] = atomicAdd(&g_rcur[tid], s_cnt[tid]);
    __syncthreads();
    if (valid) {
        g_perm[g_estart[r] + s_base[r] + lrank] = e;
        int d = dst[e];
        g_dinv[e] = g_dstart[d] + atomicAdd(&g_dcur[d], 1);
    }
}

// k-step: warp tile 64(M) x 32(N), fp16 acc. 4 A-ldsm + 2 B-ldsm + 16 HMMA.
#define KSTEP(S, aA) do { \
    uint32_t ka = (aA) + (S) * 32; \
    uint32_t am[4][4]; \
    _Pragma("unroll") \
    for (int mt = 0; mt < 4; mt++) \
        ldsm_x4(ka + mt * 16 * ROWB, am[mt][0], am[mt][1], am[mt][2], am[mt][3]); \
    uint32_t kb = bAddr + (S) * 32; \
    _Pragma("unroll") \
    for (int pr = 0; pr < 2; pr++) { \
        uint32_t b0, b1, b2, b3; \
        ldsm_x4(kb + pr * 16 * ROWB, b0, b1, b2, b3); \
        int nt = pr * 2; \
        _Pragma("unroll") \
        for (int mt = 0; mt < 4; mt++) { \
            mma16816h(acc[mt][nt],     am[mt], b0, b1); \
            mma16816h(acc[mt][nt + 1], am[mt], b2, b3); \
        } \
    } \
} while (0)

// ---------------- K5: persistent HMMA GEMM, 256-edge tiles, 512 threads ----------
// smem: A ping-pong (2x69632) + B (34816) = 174080 B -> 1 CTA/SM, 4 warps/SMSP.
__global__ __launch_bounds__(512, 1) void k_gemm(const int* __restrict__ src,
                                                 const float* __restrict__ norm) {
    extern __shared__ char dsm[];
    __shared__ int   s_src[2][TILE_M];
    __shared__ float s_nrm[2][TILE_M];
    __shared__ int   s_dinv[2][TILE_M];

    char* Abuf[2] = { dsm, dsm + ATILE };
    char* B = dsm + 2 * ATILE;

    int tid = threadIdx.x;
    int T = g_tstart[RR];
    int per = (T + GEMM_GRID - 1) / GEMM_GRID;
    int t0 = blockIdx.x * per;
    int t1 = t0 + per; if (t1 > T) t1 = T;
    if (t0 >= t1) return;

    int lane = tid & 31, w = tid >> 5;      // 16 warps
    int wm = w & 3, wn = w >> 2;            // 4 M-groups x 4 N-groups
    int rm = wm * 64;                       // warp rows [rm, rm+64)
    uint32_t aLane = (uint32_t)((rm + (lane & 15)) * ROWB + ((lane >> 4) << 4));
    uint32_t bLane = (uint32_t)((wn * 32 + ((lane >> 4) << 3) + (lane & 7)) * ROWB
                                + (((lane >> 3) & 1) << 4));
    uint32_t aBase[2] = { smem_u32(Abuf[0]) + aLane, smem_u32(Abuf[1]) + aLane };
    uint32_t bAddr = smem_u32(B) + bLane;

    int r = 0;
    while (g_tstart[r + 1] <= t0) r++;

    // ---- meta for tile t0 (buf 0, sync) ----
    if (tid < TILE_M) {
        int ebase = g_estart[r] + (t0 - g_tstart[r]) * TILE_M;
        int cnt = g_estart[r + 1] - ebase; if (cnt > TILE_M) cnt = TILE_M;
        int sv = 0, dv = -1; float nm = 0.f;
        if (tid < cnt) {
            int e = g_perm[ebase + tid];
            sv = src[e]; nm = norm[e]; dv = g_dinv[e];
        }
        s_src[0][tid] = sv; s_nrm[0][tid] = nm; s_dinv[0][tid] = dv;
    }
    __syncthreads();

    // ---- B fill for first relation + A fill for t0 ----
    {
        const char* WB = (const char*)g_WT + (size_t)r * 32768;
        #pragma unroll
        for (int it = 0; it < 4; it++) {
            int id = tid + it * 512;            // 0..2047
            int o = id >> 4, j = id & 15;
            cp16(smem_u32(B + o * ROWB + j * 16), WB + o * 256 + j * 16);
        }
        #pragma unroll
        for (int it = 0; it < 8; it++) {
            int id = tid + it * 512;            // 0..4095
            int m = id >> 4, j = id & 15;
            cp16(smem_u32(Abuf[0] + m * ROWB + j * 16),
                 (const char*)g_xh + (size_t)s_src[0][m] * 256 + j * 16);
        }
        CP_COMMIT();
    }
    CP_WAIT0();
    __syncthreads();

    int buf = 0;
    for (int t = t0; t < t1; t++) {
        bool hasNext = (t + 1 < t1);
        int rn = r;
        if (hasNext) { while (g_tstart[rn + 1] <= t + 1) rn++; }

        // 1. meta prefetch for next tile (registers)
        int m_src = 0, m_dinv = -1; float m_nrm = 0.f;
        if (hasNext && tid < TILE_M) {
            int ebase = g_estart[rn] + (t + 1 - g_tstart[rn]) * TILE_M;
            int cnt = g_estart[rn + 1] - ebase; if (cnt > TILE_M) cnt = TILE_M;
            if (tid < cnt) {
                int e = g_perm[ebase + tid];
                m_src = src[e]; m_nrm = norm[e]; m_dinv = g_dinv[e];
            }
        }

        // fp16 accumulators: [mt 0..3][nt 0..3][row-half]
        uint32_t acc[4][4][2];
        #pragma unroll
        for (int a = 0; a < 4; a++)
            #pragma unroll
            for (int b = 0; b < 4; b++) { acc[a][b][0] = 0u; acc[a][b][1] = 0u; }

        uint32_t aA = aBase[buf];

        // 2. k-steps 0-3 (hide meta LDG)
        #pragma unroll
        for (int s = 0; s < 4; s++) KSTEP(s, aA);

        // 3. publish next meta + A prefetch into other buffer
        if (hasNext && tid < TILE_M) {
            s_src[buf ^ 1][tid] = m_src;
            s_nrm[buf ^ 1][tid] = m_nrm;
            s_dinv[buf ^ 1][tid] = m_dinv;
        }
        __syncthreads();
        if (hasNext) {
            int nb = buf ^ 1;
            #pragma unroll
            for (int it = 0; it < 8; it++) {
                int id = tid + it * 512;
                int m = id >> 4, j = id & 15;
                cp16(smem_u32(Abuf[nb] + m * ROWB + j * 16),
                     (const char*)g_xh + (size_t)s_src[nb][m] * 256 + j * 16);
            }
            CP_COMMIT();
        }

        // 4. k-steps 4-7 (hide A prefetch)
        #pragma unroll
        for (int s = 4; s < 8; s++) KSTEP(s, aA);

        // 5. epilogue: unpack fp16 acc, scale by norm in fp32, store half2
        {
            int colBase = wn * 32 + (lane & 3) * 2;
            #pragma unroll
            for (int mt = 0; mt < 4; mt++) {
                int row0 = rm + mt * 16 + (lane >> 2);
                int d0 = s_dinv[buf][row0], d1 = s_dinv[buf][row0 + 8];
                float n0 = s_nrm[buf][row0], n1 = s_nrm[buf][row0 + 8];
                __half* p0 = (d0 >= 0) ? g_edge_out + (size_t)d0 * FOUT + colBase : (__half*)0;
                __half* p1 = (d1 >= 0) ? g_edge_out + (size_t)d1 * FOUT + colBase : (__half*)0;
                #pragma unroll
                for (int nt = 0; nt < 4; nt++) {
                    if (p0) {
                        uint32_t v = acc[mt][nt][0];
                        float2 f = __half22float2(*(__half2*)&v);
                        *(__half2*)(p0 + nt * 8) = __floats2half2_rn(f.x * n0, f.y * n0);
                    }
                    if (p1) {
                        uint32_t v = acc[mt][nt][1];
                        float2 f = __half22float2(*(__half2*)&v);
                        *(__half2*)(p1 + nt * 8) = __floats2half2_rn(f.x * n1, f.y * n1);
                    }
                }
            }
        }

        // 6. B reload on relation change, then drain A prefetch
        if (hasNext) {
            if (rn != r) {
                __syncthreads();   // all warps done reading B
                const char* WB = (const char*)g_WT + (size_t)rn * 32768;
                #pragma unroll
                for (int it = 0; it < 4; it++) {
                    int id = tid + it * 512;
                    int o = id >> 4, j = id & 15;
                    cp16(smem_u32(B + o * ROWB + j * 16), WB + o * 256 + j * 16);
                }
                CP_COMMIT();
                r = rn;
            }
            CP_WAIT0();
            __syncthreads();
        }
        buf ^= 1;
    }
}

// ---------------- K5b: residual GEMM g_res = relu(x @ W_res + b_res) ------------
__global__ __launch_bounds__(256) void k_res(const float* __restrict__ x,
                                             const float* __restrict__ Wres,
                                             const float* __restrict__ bres) {
    __shared__ float sAT[128][36];
    int tid = threadIdx.x;
    int n0 = blockIdx.x * 32;

    for (int idx = tid; idx < 32 * 32; idx += 256) {
        int i = idx & 31, j = idx >> 5;
        float4 v = __ldg((const float4*)(x + (size_t)(n0 + i) * FIN) + j);
        int k = j << 2;
        sAT[k + 0][i] = v.x; sAT[k + 1][i] = v.y;
        sAT[k + 2][i] = v.z; sAT[k + 3][i] = v.w;
    }
    __syncthreads();

    int tx = tid & 31, ty = tid >> 5;
    const float4* W4 = (const float4*)Wres;
    float c00=0,c01=0,c02=0,c03=0, c10=0,c11=0,c12=0,c13=0;
    float c20=0,c21=0,c22=0,c23=0, c30=0,c31=0,c32=0,c33=0;

    #pragma unroll 4
    for (int k = 0; k < 128; k++) {
        float4 b = __ldg(&W4[(k << 5) + tx]);
        float4 a = *(const float4*)&sAT[k][ty << 2];
        c00 += a.x*b.x; c01 += a.x*b.y; c02 += a.x*b.z; c03 += a.x*b.w;
        c10 += a.y*b.x; c11 += a.y*b.y; c12 += a.y*b.z; c13 += a.y*b.w;
        c20 += a.z*b.x; c21 += a.z*b.y; c22 += a.z*b.z; c23 += a.z*b.w;
        c30 += a.w*b.x; c31 += a.w*b.y; c32 += a.w*b.z; c33 += a.w*b.w;
    }

    float4 br = __ldg(&((const float4*)bres)[tx]);
    float4 rows[4] = {
        make_float4(fmaxf(c00+br.x,0.f), fmaxf(c01+br.y,0.f), fmaxf(c02+br.z,0.f), fmaxf(c03+br.w,0.f)),
        make_float4(fmaxf(c10+br.x,0.f), fmaxf(c11+br.y,0.f), fmaxf(c12+br.z,0.f), fmaxf(c13+br.w,0.f)),
        make_float4(fmaxf(c20+br.x,0.f), fmaxf(c21+br.y,0.f), fmaxf(c22+br.z,0.f), fmaxf(c23+br.w,0.f)),
        make_float4(fmaxf(c30+br.x,0.f), fmaxf(c31+br.y,0.f), fmaxf(c32+br.z,0.f), fmaxf(c33+br.w,0.f))
    };
    #pragma unroll
    for (int i = 0; i < 4; i++)
        *(float4*)(g_res + (size_t)(n0 + (ty << 2) + i) * FOUT + (tx << 2)) = rows[i];
}

// ---------------- K6: warp-per-node segmented reduce (uint4 stream) --------------
__global__ __launch_bounds__(256) void k_reduce(const float* __restrict__ h_bias) {
    int n = (blockIdx.x << 3) + (threadIdx.x >> 5);
    int lane = threadIdx.x & 31;
    int h = lane >> 4;            // 0 or 1
    int c = lane & 15;            // uint4 chunk within row (8 halves)

    int s = g_dstart[n], e = g_dstart[n + 1];
    float2 a0 = make_float2(0.f, 0.f), a1 = a0, a2 = a0, a3 = a0;

    const uint4* base = (const uint4*)g_edge_out;   // 16 uint4 per row
    for (int j = s + h; j < e; j += 2) {
        uint4 v = base[(size_t)j * 16 + c];
        float2 f;
        f = __half22float2(*(__half2*)&v.x); a0.x += f.x; a0.y += f.y;
        f = __half22float2(*(__half2*)&v.y); a1.x += f.x; a1.y += f.y;
        f = __half22float2(*(__half2*)&v.z); a2.x += f.x; a2.y += f.y;
        f = __half22float2(*(__half2*)&v.w); a3.x += f.x; a3.y += f.y;
    }
    a0.x += __shfl_down_sync(0xffffffffu, a0.x, 16);
    a0.y += __shfl_down_sync(0xffffffffu, a0.y, 16);
    a1.x += __shfl_down_sync(0xffffffffu, a1.x, 16);
    a1.y += __shfl_down_sync(0xffffffffu, a1.y, 16);
    a2.x += __shfl_down_sync(0xffffffffu, a2.x, 16);
    a2.y += __shfl_down_sync(0xffffffffu, a2.y, 16);
    a3.x += __shfl_down_sync(0xffffffffu, a3.x, 16);
    a3.y += __shfl_down_sync(0xffffffffu, a3.y, 16);

    if (h == 0) {
        const float4* bia = (const float4*)h_bias;
        float4 b0 = __ldg(&bia[c * 2]), b1 = __ldg(&bia[c * 2 + 1]);
        float4 r0 = ((const float4*)g_res)[(size_t)n * 32 + c * 2];
        float4 r1 = ((const float4*)g_res)[(size_t)n * 32 + c * 2 + 1];
        float4 o0, o1;
        o0.x = fmaxf(a0.x + b0.x, 0.f) + r0.x;
        o0.y = fmaxf(a0.y + b0.y, 0.f) + r0.y;
        o0.z = fmaxf(a1.x + b0.z, 0.f) + r0.z;
        o0.w = fmaxf(a1.y + b0.w, 0.f) + r0.w;
        o1.x = fmaxf(a2.x + b1.x, 0.f) + r1.x;
        o1.y = fmaxf(a2.y + b1.y, 0.f) + r1.y;
        o1.z = fmaxf(a3.x + b1.z, 0.f) + r1.z;
        o1.w = fmaxf(a3.y + b1.w, 0.f) + r1.w;
        ((float4*)g_h)[(size_t)n * 32 + c * 2]     = o0;
        ((float4*)g_h)[(size_t)n * 32 + c * 2 + 1] = o1;
    }
}

// ---------------- K7/K8/K9: BN -----------------------------------------------------
__global__ __launch_bounds__(128) void k_bnsum() {
    int b = blockIdx.x, o = threadIdx.x;
    float s = 0.f, sq = 0.f;
    int r0 = b * (NN / NBN), r1 = r0 + (NN / NBN);
    for (int n = r0; n < r1; n++) {
        float v = g_h[(size_t)n * FOUT + o];
        s += v; sq += v * v;
    }
    g_psum[b * FOUT + o] = s;
    g_psq[b * FOUT + o] = sq;
}

__global__ __launch_bounds__(128) void k_bnfin(const float* __restrict__ gamma,
                                               const float* __restrict__ beta) {
    int o = threadIdx.x;
    float s = 0.f, sq = 0.f;
    for (int b = 0; b < NBN; b++) { s += g_psum[b * FOUT + o]; sq += g_psq[b * FOUT + o]; }
    float mean = s / (float)NN;
    float var = sq / (float)NN - mean * mean;
    float sc = gamma[o] * rsqrtf(var + 1e-5f);
    g_scale[o] = sc;
    g_shift[o] = beta[o] - mean * sc;
}

__global__ void k_out(float* __restrict__ out) {
    int i = blockIdx.x * 256 + threadIdx.x;          // float4 index
    if (i < NN * FOUT / 4) {
        float4 v = ((const float4*)g_h)[i];
        int c4 = i & 31;
        float4 sc = ((const float4*)g_scale)[c4];
        float4 sh = ((const float4*)g_shift)[c4];
        float4 o;
        o.x = v.x * sc.x + sh.x;
        o.y = v.y * sc.y + sh.y;
        o.z = v.z * sc.z + sh.z;
        o.w = v.w * sc.w + sh.w;
        ((float4*)out)[i] = o;
    }
}

// ---------------- launch -------------------------------------------------------------
extern "C" void kernel_launch(void* const* d_in, const int* in_sizes, int n_in,
                              void* d_out, int out_size) {
    const float* node_feats = (const float*)d_in[0];
    const int*   src        = (const int*)d_in[1];
    const int*   dst        = (const int*)d_in[2];
    const int*   etype      = (const int*)d_in[3];
    const float* norm       = (const float*)d_in[4];
    const float* basis      = (const float*)d_in[5];
    const float* comp       = (const float*)d_in[6];
    const float* h_bias     = (const float*)d_in[7];
    const float* W_res      = (const float*)d_in[8];
    const float* b_res      = (const float*)d_in[9];
    const float* gamma      = (const float*)d_in[10];
    const float* beta       = (const float*)d_in[11];
    float* out = (float*)d_out;

    const int DSMEM   = 2 * ATILE + BTILE;              // 174080 B -> 1 CTA/SM
    const int KW_SMEM = (BB * FIN + RR * BB) * 4;       // 50180 B
    cudaFuncSetAttribute(k_gemm, cudaFuncAttributeMaxDynamicSharedMemorySize, DSMEM);
    cudaFuncSetAttribute(k_w, cudaFuncAttributeMaxDynamicSharedMemorySize, KW_SMEM);

    k_w<<<FIN, 128, KW_SMEM>>>(basis, comp);
    k_xcvt<<<(NN * FIN / 2 + 255) / 256, 256>>>(node_feats);
    k_hist<<<(EE + 255) / 256, 256>>>(etype, dst);
    k_scan1<<<20, 1024>>>();
    k_scan2<<<1, 32>>>();
    k_scan3<<<20, 1024>>>();
    k_scatter<<<(EE + 255) / 256, 256>>>(etype, dst);
    k_gemm<<<GEMM_GRID, 512, DSMEM>>>(src, norm);
    k_res<<<NN / 32, 256>>>(node_feats, W_res, b_res);
    k_reduce<<<NN / 8, 256>>>(h_bias);
    k_bnsum<<<NBN, 128>>>();
    k_bnfin<<<1, 128>>>(gamma, beta);
    k_out<<<(NN * FOUT / 4 + 255) / 256, 256>>>(out);
    (void)in_sizes; (void)n_in; (void)out_size;
}

// round 13
// speedup vs baseline: 1.2251x; 1.2251x over previous
#include <cuda_runtime.h>
#include <cuda_fp16.h>
#include <stdint.h>

// Problem constants
#define NN   20000
#define EE   640000
#define FIN  128
#define FOUT 128
#define RR   65
#define BB   65
#define TILE_M 128
#define NBN  200

#define ROWB 272                  // bytes per smem tile row (136 halves, padded)
#define ATILE (128 * ROWB)        // 34816 B
#define GEMM_GRID 296             // 2 CTAs per SM
#define NTSYN ((NN + TILE_M - 1) / TILE_M)   // synthetic residual tiles (157)

// ---------------- scratch (__device__ globals) ------------------------------
__device__ __align__(16) __half g_WT[(size_t)(RR + 1) * FOUT * FIN]; // [r][o][k]; slot RR = W_res
__device__ __align__(16) __half g_xh[(size_t)NN * FIN];
__device__ int   g_cnt[RR];
__device__ int   g_rcur[RR];
__device__ int   g_estart[RR + 1];
__device__ int   g_tstart[RR + 2];               // [RR+1] = total incl synthetic
__device__ int   g_perm[EE];
__device__ int   g_dcnt[NN];
__device__ int   g_dcur[NN];
__device__ int   g_dstart[NN + 1];
__device__ int   g_bsum[20];
__device__ int   g_boff[20];
__device__ int   g_dinv[EE];                     // edge -> dst-sorted rank
__device__ __align__(16) __half g_edge_out[(size_t)(EE + NN) * FOUT]; // + residual rows
__device__ float g_h[(size_t)NN * FOUT];
__device__ float g_psum[NBN * FOUT];
__device__ float g_psq[NBN * FOUT];
__device__ float g_scale[FOUT];
__device__ float g_shift[FOUT];

// ---------------- helpers ----------------------------------------------------
__device__ __forceinline__ uint32_t smem_u32(const void* p) {
    uint32_t a;
    asm("{ .reg .u64 t; cvta.to.shared.u64 t, %1; cvt.u32.u64 %0, t; }"
        : "=r"(a) : "l"(p));
    return a;
}

__device__ __forceinline__ void ldsm_x4(uint32_t addr, uint32_t& r0, uint32_t& r1,
                                        uint32_t& r2, uint32_t& r3) {
    asm volatile("ldmatrix.sync.aligned.m8n8.x4.shared.b16 {%0,%1,%2,%3}, [%4];"
                 : "=r"(r0), "=r"(r1), "=r"(r2), "=r"(r3) : "r"(addr));
}

// fp16-accumulator HMMA
__device__ __forceinline__ void mma16816h(uint32_t* c, const uint32_t* a,
                                          uint32_t b0, uint32_t b1) {
    asm volatile(
        "mma.sync.aligned.m16n8k16.row.col.f16.f16.f16.f16 "
        "{%0,%1}, {%2,%3,%4,%5}, {%6,%7}, {%0,%1};"
        : "+r"(c[0]), "+r"(c[1])
        : "r"(a[0]), "r"(a[1]), "r"(a[2]), "r"(a[3]), "r"(b0), "r"(b1));
}

__device__ __forceinline__ void cp16(uint32_t dst, const void* src) {
    asm volatile("cp.async.cg.shared.global [%0], [%1], 16;"
                 :: "r"(dst), "l"(src) : "memory");
}
#define CP_COMMIT() asm volatile("cp.async.commit_group;" ::: "memory")
#define CP_WAIT0()  asm volatile("cp.async.wait_group 0;" ::: "memory")

// ---------------- K0: zero counters (must precede k_pre's hist) -----------------
__global__ void k_zero() {
    int i = blockIdx.x * 256 + threadIdx.x;
    if (i < NN) { g_dcnt[i] = 0; g_dcur[i] = 0; }
    if (i < RR) { g_cnt[i] = 0; g_rcur[i] = 0; }
}

// ---------------- K1: WT fp16 = (comp x basis) transposed, basis read once -----
__global__ __launch_bounds__(128) void k_w(const float* __restrict__ basis,
                                           const float* __restrict__ comp) {
    extern __shared__ float swm[];
    float* sb = swm;              // [BB][FIN] = basis[b][i][o] for fixed i
    float* sc = swm + BB * FIN;   // [RR*BB]

    int i = blockIdx.x, o = threadIdx.x;

    for (int b = 0; b < BB; b++)
        sb[b * FIN + o] = basis[(size_t)b * FIN * FOUT + (size_t)i * FOUT + o];
    for (int idx = o; idx < RR * BB; idx += 128)
        sc[idx] = comp[idx];
    __syncthreads();

    float acc[RR];
    #pragma unroll
    for (int r = 0; r < RR; r++) acc[r] = 0.f;

    for (int b = 0; b < BB; b++) {
        float sv = sb[b * FIN + o];
        #pragma unroll
        for (int r = 0; r < RR; r++)
            acc[r] += sc[r * BB + b] * sv;
    }

    #pragma unroll 1
    for (int r = 0; r < RR; r++)
        g_WT[((size_t)r * FOUT + o) * FIN + i] = __float2half(acc[r]);
}

// ---------------- K2: merged preprocessing ---------------------------------------
// - x -> fp16 (all blocks)
// - W_res -> fp16 transposed into g_WT slot RR (first 64 blocks)
// - relation + dst histograms (first 2500 blocks)
__global__ void k_pre(const float* __restrict__ x,
                      const int* __restrict__ etype,
                      const int* __restrict__ dst,
                      const float* __restrict__ Wres) {
    __shared__ int sh[RR];
    int tid = threadIdx.x;
    int gb = blockIdx.x;
    int i = gb * 256 + tid;

    if (i < NN * FIN / 2) {
        float2 v = ((const float2*)x)[i];
        ((__half2*)g_xh)[i] = __floats2half2_rn(v.x, v.y);
    }
    if (i < FIN * FOUT) {
        int k = i >> 7, o = i & 127;
        g_WT[((size_t)RR * FOUT + o) * FIN + k] = __float2half(Wres[i]);
    }
    if (gb < (EE + 255) / 256) {
        if (tid < RR) sh[tid] = 0;
        __syncthreads();
        if (i < EE) {
            atomicAdd(&sh[etype[i]], 1);
            atomicAdd(&g_dcnt[dst[i]], 1);
        }
        __syncthreads();
        if (tid < RR && sh[tid]) atomicAdd(&g_cnt[tid], sh[tid]);
    }
}

// ---------------- K3a: local scans (20 blocks x 1000 counts) --------------------
__global__ __launch_bounds__(1024) void k_scan1() {
    __shared__ int sa[1024], sb2[1024];
    int t = threadIdx.x;
    int g = blockIdx.x * 1000;
    int v = (t < 1000) ? g_dcnt[g + t] : 0;
    sa[t] = v;
    __syncthreads();
    int* in = sa; int* out = sb2;
    #pragma unroll
    for (int off = 1; off < 1024; off <<= 1) {
        out[t] = in[t] + ((t >= off) ? in[t - off] : 0);
        __syncthreads();
        int* tmp = in; in = out; out = tmp;
    }
    if (t < 1000) g_dstart[g + t] = in[t] - v;      // local exclusive
    if (t == 999) g_bsum[blockIdx.x] = in[t];       // block total
}

// ---------------- K3b: block offsets + relation scan ------------------------------
__global__ void k_scan2() {
    if (threadIdx.x == 0) {
        int run = 0;
        for (int k = 0; k < 20; k++) { g_boff[k] = run; run += g_bsum[k]; }
        g_dstart[NN] = run;
        int es = 0, ts = 0;
        for (int r = 0; r < RR; r++) {
            g_estart[r] = es; g_tstart[r] = ts;
            es += g_cnt[r];
            ts += (g_cnt[r] + TILE_M - 1) / TILE_M;
        }
        g_estart[RR] = es;
        g_tstart[RR] = ts;
        g_tstart[RR + 1] = ts + NTSYN;     // synthetic residual tiles appended
    }
}

// ---------------- K3c: add block offsets -------------------------------------------
__global__ __launch_bounds__(1024) void k_scan3() {
    int t = threadIdx.x;
    if (t < 1000) g_dstart[blockIdx.x * 1000 + t] += g_boff[blockIdx.x];
}

// ---------------- K4: scatter ------------------------------------------------------
__global__ void k_scatter(const int* __restrict__ etype, const int* __restrict__ dst) {
    __shared__ int s_cnt[RR], s_base[RR];
    int tid = threadIdx.x;
    if (tid < RR) s_cnt[tid] = 0;
    __syncthreads();
    int e = blockIdx.x * 256 + tid;
    bool valid = (e < EE);
    int r = 0, lrank = 0;
    if (valid) { r = etype[e]; lrank = atomicAdd(&s_cnt[r], 1); }
    __syncthreads();
    if (tid < RR && s_cnt[tid] > 0) s_base[tid] = atomicAdd(&g_rcur[tid], s_cnt[tid]);
    __syncthreads();
    if (valid) {
        g_perm[g_estart[r] + s_base[r] + lrank] = e;
        int d = dst[e];
        g_dinv[e] = g_dstart[d] + atomicAdd(&g_dcur[d], 1);
    }
}

// single-product k-step, fp16 accumulators
#define KSTEP(S, aA) do { \
    uint32_t ka = (aA) + (S) * 32; \
    uint32_t a0[4], a1[4]; \
    ldsm_x4(ka,             a0[0], a0[1], a0[2], a0[3]); \
    ldsm_x4(ka + 16 * ROWB, a1[0], a1[1], a1[2], a1[3]); \
    uint32_t kb = bAddr + (S) * 32; \
    _Pragma("unroll") \
    for (int pr = 0; pr < 4; pr++) { \
        uint32_t b0, b1, b2, b3; \
        ldsm_x4(kb + pr * 16 * ROWB, b0, b1, b2, b3); \
        int nt = pr * 2; \
        mma16816h(acc[0][nt],     a0, b0, b1); \
        mma16816h(acc[1][nt],     a1, b0, b1); \
        mma16816h(acc[0][nt + 1], a0, b2, b3); \
        mma16816h(acc[1][nt + 1], a1, b2, b3); \
    } \
} while (0)

// ---------------- K5: persistent HMMA GEMM (edges + residual-as-relation-65) -----
__global__ __launch_bounds__(256, 2) void k_gemm(const int* __restrict__ src,
                                                 const float* __restrict__ norm) {
    extern __shared__ char dsm[];
    __shared__ int   s_src[2][TILE_M];
    __shared__ float s_nrm[2][TILE_M];
    __shared__ int   s_dinv[2][TILE_M];

    char* Abuf[2] = { dsm, dsm + ATILE };
    char* B = dsm + 2 * ATILE;

    int tid = threadIdx.x;
    int T = g_tstart[RR + 1];                 // includes synthetic tiles
    int per = (T + GEMM_GRID - 1) / GEMM_GRID;
    int t0 = blockIdx.x * per;
    int t1 = t0 + per; if (t1 > T) t1 = T;
    if (t0 >= t1) return;

    int lane = tid & 31, w = tid >> 5;
    int wm = w & 3, wn = w >> 2;
    int rm = wm * 32;
    uint32_t aLane = (uint32_t)((rm + (lane & 15)) * ROWB + ((lane >> 4) << 4));
    uint32_t bLane = (uint32_t)((wn * 64 + ((lane >> 4) << 3) + (lane & 7)) * ROWB
                                + (((lane >> 3) & 1) << 4));
    uint32_t aBase[2] = { smem_u32(Abuf[0]) + aLane, smem_u32(Abuf[1]) + aLane };
    uint32_t bAddr = smem_u32(B) + bLane;

    int r = 0;
    while (g_tstart[r + 1] <= t0) r++;        // r may reach RR (residual)

    // ---- meta for tile t0 (buf 0, sync) ----
    if (tid < TILE_M) {
        int sv = 0, dv = -1; float nm = 0.f;
        if (r < RR) {
            int ebase = g_estart[r] + (t0 - g_tstart[r]) * TILE_M;
            int cnt = g_estart[r + 1] - ebase; if (cnt > TILE_M) cnt = TILE_M;
            if (tid < cnt) {
                int e = g_perm[ebase + tid];
                sv = src[e]; nm = norm[e]; dv = g_dinv[e];
            }
        } else {
            int n = (t0 - g_tstart[RR]) * TILE_M + tid;
            if (n < NN) { sv = n; nm = 1.f; dv = EE + n; }
        }
        s_src[0][tid] = sv; s_nrm[0][tid] = nm; s_dinv[0][tid] = dv;
    }
    __syncthreads();

    // ---- B fill for first relation + A fill for t0 ----
    {
        const char* WB = (const char*)g_WT + (size_t)r * 32768;
        #pragma unroll
        for (int it = 0; it < 8; it++) {
            int id = tid + it * 256;
            int o = id >> 4, j = id & 15;
            cp16(smem_u32(B + o * ROWB + j * 16), WB + o * 256 + j * 16);
        }
        #pragma unroll
        for (int it = 0; it < 8; it++) {
            int id = tid + it * 256;
            int m = id >> 4, j = id & 15;
            cp16(smem_u32(Abuf[0] + m * ROWB + j * 16),
                 (const char*)g_xh + (size_t)s_src[0][m] * 256 + j * 16);
        }
        CP_COMMIT();
    }
    CP_WAIT0();
    __syncthreads();

    int buf = 0;
    for (int t = t0; t < t1; t++) {
        bool hasNext = (t + 1 < t1);
        int rn = r;
        if (hasNext) { while (g_tstart[rn + 1] <= t + 1) rn++; }

        // 1. meta prefetch for next tile (registers)
        int m_src = 0, m_dinv = -1; float m_nrm = 0.f;
        if (hasNext && tid < TILE_M) {
            if (rn < RR) {
                int ebase = g_estart[rn] + (t + 1 - g_tstart[rn]) * TILE_M;
                int cnt = g_estart[rn + 1] - ebase; if (cnt > TILE_M) cnt = TILE_M;
                if (tid < cnt) {
                    int e = g_perm[ebase + tid];
                    m_src = src[e]; m_nrm = norm[e]; m_dinv = g_dinv[e];
                }
            } else {
                int n = (t + 1 - g_tstart[RR]) * TILE_M + tid;
                if (n < NN) { m_src = n; m_nrm = 1.f; m_dinv = EE + n; }
            }
        }

        // fp16 accumulators: [mt][nt][row-half]
        uint32_t acc[2][8][2];
        #pragma unroll
        for (int a = 0; a < 2; a++)
            #pragma unroll
            for (int b = 0; b < 8; b++) { acc[a][b][0] = 0u; acc[a][b][1] = 0u; }

        uint32_t aA = aBase[buf];

        // 2. k-steps 0-3 (hide meta LDG)
        #pragma unroll
        for (int s = 0; s < 4; s++) KSTEP(s, aA);

        // 3. publish next meta + A prefetch into other buffer
        if (hasNext && tid < TILE_M) {
            s_src[buf ^ 1][tid] = m_src;
            s_nrm[buf ^ 1][tid] = m_nrm;
            s_dinv[buf ^ 1][tid] = m_dinv;
        }
        __syncthreads();
        if (hasNext) {
            int nb = buf ^ 1;
            #pragma unroll
            for (int it = 0; it < 8; it++) {
                int id = tid + it * 256;
                int m = id >> 4, j = id & 15;
                cp16(smem_u32(Abuf[nb] + m * ROWB + j * 16),
                     (const char*)g_xh + (size_t)s_src[nb][m] * 256 + j * 16);
            }
            CP_COMMIT();
        }

        // 4. k-steps 4-7 (hide A prefetch)
        #pragma unroll
        for (int s = 4; s < 8; s++) KSTEP(s, aA);

        // 5. epilogue: unpack fp16 acc, scale by norm in fp32, store half2
        {
            int colBase = wn * 64 + (lane & 3) * 2;
            #pragma unroll
            for (int mt = 0; mt < 2; mt++) {
                int row0 = rm + mt * 16 + (lane >> 2);
                int d0 = s_dinv[buf][row0], d1 = s_dinv[buf][row0 + 8];
                float n0 = s_nrm[buf][row0], n1 = s_nrm[buf][row0 + 8];
                __half* p0 = (d0 >= 0) ? g_edge_out + (size_t)d0 * FOUT + colBase : (__half*)0;
                __half* p1 = (d1 >= 0) ? g_edge_out + (size_t)d1 * FOUT + colBase : (__half*)0;
                #pragma unroll
                for (int nt = 0; nt < 8; nt++) {
                    if (p0) {
                        uint32_t v = acc[mt][nt][0];
                        float2 f = __half22float2(*(__half2*)&v);
                        *(__half2*)(p0 + nt * 8) = __floats2half2_rn(f.x * n0, f.y * n0);
                    }
                    if (p1) {
                        uint32_t v = acc[mt][nt][1];
                        float2 f = __half22float2(*(__half2*)&v);
                        *(__half2*)(p1 + nt * 8) = __floats2half2_rn(f.x * n1, f.y * n1);
                    }
                }
            }
        }

        // 6. B reload on relation change, then drain A prefetch
        if (hasNext) {
            if (rn != r) {
                __syncthreads();   // all warps done reading B
                const char* WB = (const char*)g_WT + (size_t)rn * 32768;
                #pragma unroll
                for (int it = 0; it < 8; it++) {
                    int id = tid + it * 256;
                    int o = id >> 4, j = id & 15;
                    cp16(smem_u32(B + o * ROWB + j * 16), WB + o * 256 + j * 16);
                }
                CP_COMMIT();
                r = rn;
            }
            CP_WAIT0();
            __syncthreads();
        }
        buf ^= 1;
    }
}

// ---------------- K6: warp-per-node reduce + bias/relu + residual bias/relu ------
__global__ __launch_bounds__(256) void k_reduce(const float* __restrict__ h_bias,
                                                const float* __restrict__ b_res) {
    int n = (blockIdx.x << 3) + (threadIdx.x >> 5);
    int lane = threadIdx.x & 31;
    int h = lane >> 4;            // 0 or 1
    int c = lane & 15;            // uint4 chunk within row (8 halves)

    int s = g_dstart[n], e = g_dstart[n + 1];
    float2 a0 = make_float2(0.f, 0.f), a1 = a0, a2 = a0, a3 = a0;

    const uint4* base = (const uint4*)g_edge_out;   // 16 uint4 per row
    for (int j = s + h; j < e; j += 2) {
        uint4 v = base[(size_t)j * 16 + c];
        float2 f;
        f = __half22float2(*(__half2*)&v.x); a0.x += f.x; a0.y += f.y;
        f = __half22float2(*(__half2*)&v.y); a1.x += f.x; a1.y += f.y;
        f = __half22float2(*(__half2*)&v.z); a2.x += f.x; a2.y += f.y;
        f = __half22float2(*(__half2*)&v.w); a3.x += f.x; a3.y += f.y;
    }
    a0.x += __shfl_down_sync(0xffffffffu, a0.x, 16);
    a0.y += __shfl_down_sync(0xffffffffu, a0.y, 16);
    a1.x += __shfl_down_sync(0xffffffffu, a1.x, 16);
    a1.y += __shfl_down_sync(0xffffffffu, a1.y, 16);
    a2.x += __shfl_down_sync(0xffffffffu, a2.x, 16);
    a2.y += __shfl_down_sync(0xffffffffu, a2.y, 16);
    a3.x += __shfl_down_sync(0xffffffffu, a3.x, 16);
    a3.y += __shfl_down_sync(0xffffffffu, a3.y, 16);

    if (h == 0) {
        // conv bias
        const float4* bia = (const float4*)h_bias;
        float4 b0 = __ldg(&bia[c * 2]), b1 = __ldg(&bia[c * 2 + 1]);
        // residual raw row (relation-65 output) + its bias
        uint4 rv = base[(size_t)(EE + n) * 16 + c];
        float2 rf0 = __half22float2(*(__half2*)&rv.x);
        float2 rf1 = __half22float2(*(__half2*)&rv.y);
        float2 rf2 = __half22float2(*(__half2*)&rv.z);
        float2 rf3 = __half22float2(*(__half2*)&rv.w);
        const float4* brp = (const float4*)b_res;
        float4 br0 = __ldg(&brp[c * 2]), br1 = __ldg(&brp[c * 2 + 1]);

        float4 o0, o1;
        o0.x = fmaxf(a0.x + b0.x, 0.f) + fmaxf(rf0.x + br0.x, 0.f);
        o0.y = fmaxf(a0.y + b0.y, 0.f) + fmaxf(rf0.y + br0.y, 0.f);
        o0.z = fmaxf(a1.x + b0.z, 0.f) + fmaxf(rf1.x + br0.z, 0.f);
        o0.w = fmaxf(a1.y + b0.w, 0.f) + fmaxf(rf1.y + br0.w, 0.f);
        o1.x = fmaxf(a2.x + b1.x, 0.f) + fmaxf(rf2.x + br1.x, 0.f);
        o1.y = fmaxf(a2.y + b1.y, 0.f) + fmaxf(rf2.y + br1.y, 0.f);
        o1.z = fmaxf(a3.x + b1.z, 0.f) + fmaxf(rf3.x + br1.z, 0.f);
        o1.w = fmaxf(a3.y + b1.w, 0.f) + fmaxf(rf3.y + br1.w, 0.f);
        ((float4*)g_h)[(size_t)n * 32 + c * 2]     = o0;
        ((float4*)g_h)[(size_t)n * 32 + c * 2 + 1] = o1;
    }
}

// ---------------- K7/K8/K9: BN -----------------------------------------------------
__global__ __launch_bounds__(128) void k_bnsum() {
    int b = blockIdx.x, o = threadIdx.x;
    float s = 0.f, sq = 0.f;
    int r0 = b * (NN / NBN), r1 = r0 + (NN / NBN);
    for (int n = r0; n < r1; n++) {
        float v = g_h[(size_t)n * FOUT + o];
        s += v; sq += v * v;
    }
    g_psum[b * FOUT + o] = s;
    g_psq[b * FOUT + o] = sq;
}

__global__ __launch_bounds__(128) void k_bnfin(const float* __restrict__ gamma,
                                               const float* __restrict__ beta) {
    int o = threadIdx.x;
    float s = 0.f, sq = 0.f;
    for (int b = 0; b < NBN; b++) { s += g_psum[b * FOUT + o]; sq += g_psq[b * FOUT + o]; }
    float mean = s / (float)NN;
    float var = sq / (float)NN - mean * mean;
    float sc = gamma[o] * rsqrtf(var + 1e-5f);
    g_scale[o] = sc;
    g_shift[o] = beta[o] - mean * sc;
}

__global__ void k_out(float* __restrict__ out) {
    int i = blockIdx.x * 256 + threadIdx.x;          // float4 index
    if (i < NN * FOUT / 4) {
        float4 v = ((const float4*)g_h)[i];
        int c4 = i & 31;
        float4 sc = ((const float4*)g_scale)[c4];
        float4 sh = ((const float4*)g_shift)[c4];
        float4 o;
        o.x = v.x * sc.x + sh.x;
        o.y = v.y * sc.y + sh.y;
        o.z = v.z * sc.z + sh.z;
        o.w = v.w * sc.w + sh.w;
        ((float4*)out)[i] = o;
    }
}

// ---------------- launch -------------------------------------------------------------
extern "C" void kernel_launch(void* const* d_in, const int* in_sizes, int n_in,
                              void* d_out, int out_size) {
    const float* node_feats = (const float*)d_in[0];
    const int*   src        = (const int*)d_in[1];
    const int*   dst        = (const int*)d_in[2];
    const int*   etype      = (const int*)d_in[3];
    const float* norm       = (const float*)d_in[4];
    const float* basis      = (const float*)d_in[5];
    const float* comp       = (const float*)d_in[6];
    const float* h_bias     = (const float*)d_in[7];
    const float* W_res      = (const float*)d_in[8];
    const float* b_res      = (const float*)d_in[9];
    const float* gamma      = (const float*)d_in[10];
    const float* beta       = (const float*)d_in[11];
    float* out = (float*)d_out;

    const int DSMEM   = 3 * ATILE;                      // 104448 B -> 2 CTAs/SM
    const int KW_SMEM = (BB * FIN + RR * BB) * 4;       // 50180 B
    cudaFuncSetAttribute(k_gemm, cudaFuncAttributeMaxDynamicSharedMemorySize, DSMEM);
    cudaFuncSetAttribute(k_w, cudaFuncAttributeMaxDynamicSharedMemorySize, KW_SMEM);

    k_zero<<<(NN + 255) / 256, 256>>>();
    k_w<<<FIN, 128, KW_SMEM>>>(basis, comp);
    k_pre<<<(NN * FIN / 2 + 255) / 256, 256>>>(node_feats, etype, dst, W_res);
    k_scan1<<<20, 1024>>>();
    k_scan2<<<1, 32>>>();
    k_scan3<<<20, 1024>>>();
    k_scatter<<<(EE + 255) / 256, 256>>>(etype, dst);
    k_gemm<<<GEMM_GRID, 256, DSMEM>>>(src, norm);
    k_reduce<<<NN / 8, 256>>>(h_bias, b_res);
    k_bnsum<<<NBN, 128>>>();
    k_bnfin<<<1, 128>>>(gamma, beta);
    k_out<<<(NN * FOUT / 4 + 255) / 256, 256>>>(out);
    (void)in_sizes; (void)n_in; (void)out_size;
}